// round 11
// baseline (speedup 1.0000x reference)
#include <cuda_runtime.h>

#define N_NODES 100000
#define N_EDGES 1600000
#define NFEAT   48
#define HIDDEN  256
#define TILE    128   // nodes per block in k_dot

// Scratch (no device allocation allowed -> __device__ globals)
__device__ float        g_w[NFEAT];     // fused W1@W2
__device__ float        g_c;            // fused bias term
__device__ unsigned int g_deg[N_NODES]; // edge-in count (self loop added in k_z)
__device__ float        g_dinv[N_NODES];
__device__ float        g_z[N_NODES];   // y = x.w, then z = y*dinv (in place)

// ---- side stream A1: w = W1@W2, c = bias*sum(W2)+b2 ----
__global__ void k_fuse_w(const float* __restrict__ W1,
                         const float* __restrict__ bias,
                         const float* __restrict__ W2,
                         const float* __restrict__ b2) {
    __shared__ float s_w2[HIDDEN];
    int t = threadIdx.x;              // blockDim == HIDDEN == 256
    s_w2[t] = W2[t];
    __syncthreads();
    if (t < NFEAT) {
        const float* r = W1 + t * HIDDEN;
        float acc = 0.f;
#pragma unroll 8
        for (int h = 0; h < HIDDEN; ++h) acc = fmaf(r[h], s_w2[h], acc);
        g_w[t] = acc;
    }
    if (t == 0) {
        float s = 0.f;
        for (int h = 0; h < HIDDEN; ++h) s += s_w2[h];
        g_c = bias[0] * s + b2[0];
    }
}

// ---- side stream A2: y[i] = x[i].w  (coalesced via padded smem tile) ----
__global__ void __launch_bounds__(TILE) k_dot(const float* __restrict__ x) {
    __shared__ float sx[TILE * 49];   // stride-49 padding: conflict-free reads
    __shared__ float sw[NFEAT];

    int t    = threadIdx.x;
    int tile = blockIdx.x * TILE;
    int nn   = min(TILE, N_NODES - tile);

    if (t < NFEAT) sw[t] = g_w[t];

    const float4* src = reinterpret_cast<const float4*>(x + (size_t)tile * NFEAT);
    int nf4 = nn * (NFEAT / 4);
    for (int idx = t; idx < nf4; idx += TILE) {
        float4 v = __ldg(&src[idx]);
        int node = idx / 12;
        int f4   = idx - node * 12;
        float* d = &sx[node * 49 + f4 * 4];
        d[0] = v.x; d[1] = v.y; d[2] = v.z; d[3] = v.w;
    }
    __syncthreads();

    if (t < nn) {
        const float* r = &sx[t * 49];
        float a0 = 0.f, a1 = 0.f, a2 = 0.f, a3 = 0.f;
#pragma unroll
        for (int k = 0; k < NFEAT; k += 4) {
            a0 = fmaf(r[k + 0], sw[k + 0], a0);
            a1 = fmaf(r[k + 1], sw[k + 1], a1);
            a2 = fmaf(r[k + 2], sw[k + 2], a2);
            a3 = fmaf(r[k + 3], sw[k + 3], a3);
        }
        g_z[tile + t] = (a0 + a1) + (a2 + a3);   // y (dinv applied in k_z)
    }
}

// ---- main stream: degree count (u32), 4 edges per thread ----
__global__ void k_count(const int* __restrict__ ei) {
    int t = blockIdx.x * blockDim.x + threadIdx.x;
    if (t < N_EDGES / 4) {
        const int4* cols = reinterpret_cast<const int4*>(ei + N_EDGES);
        int4 c = __ldg(&cols[t]);
        atomicAdd(&g_deg[c.x], 1u);
        atomicAdd(&g_deg[c.y], 1u);
        atomicAdd(&g_deg[c.z], 1u);
        atomicAdd(&g_deg[c.w], 1u);
    }
}

// ---- join (PDL): dinv = rsqrt(deg+1); z = y*dinv; out = z*dinv + c ----
// Scalar granularity: 391 blocks / 100K threads so the L2-latency chains are
// hidden by warp parallelism (R10: float4 version was 4.9us at occ 12%).
__global__ void k_z(float* __restrict__ out) {
    cudaGridDependencySynchronize();   // PDL: wait for k_count's g_deg
    int i = blockIdx.x * blockDim.x + threadIdx.x;
    if (i < N_NODES) {
        float di = rsqrtf((float)(g_deg[i] + 1u));
        float z  = g_z[i] * di;
        float c  = g_c;
        g_dinv[i] = di;
        g_z[i]    = z;
        out[i]    = fmaf(z, di, c);    // self-loop + final norm + bias folded
    }
}

// ---- scatter + final fused (PDL): out[col] += z[row] * dinv[col] ----
__global__ void k_scatter(const int* __restrict__ ei, float* __restrict__ out) {
    cudaGridDependencySynchronize();   // PDL: wait for k_z's g_z/g_dinv/out
    int t = blockIdx.x * blockDim.x + threadIdx.x;
    if (t < N_EDGES / 4) {
        const int4* rows = reinterpret_cast<const int4*>(ei);
        const int4* cols = reinterpret_cast<const int4*>(ei + N_EDGES);
        int4 r = __ldg(&rows[t]);
        int4 c = __ldg(&cols[t]);
        float z0 = __ldg(&g_z[r.x]);
        float z1 = __ldg(&g_z[r.y]);
        float z2 = __ldg(&g_z[r.z]);
        float z3 = __ldg(&g_z[r.w]);
        float d0 = __ldg(&g_dinv[c.x]);
        float d1 = __ldg(&g_dinv[c.y]);
        float d2 = __ldg(&g_dinv[c.z]);
        float d3 = __ldg(&g_dinv[c.w]);
        atomicAdd(&out[c.x], z0 * d0);
        atomicAdd(&out[c.y], z1 * d1);
        atomicAdd(&out[c.z], z2 * d2);
        atomicAdd(&out[c.w], z3 * d3);
    }
}

extern "C" void kernel_launch(void* const* d_in, const int* in_sizes, int n_in,
                              void* d_out, int out_size) {
    const float* x    = (const float*)d_in[0];
    const int*   ei   = (const int*)  d_in[1];
    const float* W1   = (const float*)d_in[2];
    const float* bias = (const float*)d_in[3];
    const float* W2   = (const float*)d_in[4];
    const float* b2   = (const float*)d_in[5];
    float* out = (float*)d_out;

    const int TB = 256;
    const int nb_n    = (N_NODES + TB - 1) / TB;       // 391
    const int nb_e4   = (N_EDGES / 4 + TB - 1) / TB;   // 1563
    const int nb_node = (N_NODES + TILE - 1) / TILE;   // 782

    // Degree init: memset node (cheap) instead of a kernel.
    void* deg_ptr = nullptr;
    cudaGetSymbolAddress(&deg_ptr, g_deg);
    cudaMemsetAsync(deg_ptr, 0, N_NODES * sizeof(unsigned int), 0);

    // Fork: (fuse_w -> dot) DRAM-bound chain overlaps (memset -> count)
    // atomic-bound chain. Host-side stream/event objects only (no device
    // memory); leaked intentionally - kernel_launch runs a bounded number
    // of times (correctness + capture).
    cudaStream_t s1;
    cudaEvent_t  eFork, eJoin;
    cudaStreamCreateWithFlags(&s1, cudaStreamNonBlocking);
    cudaEventCreateWithFlags(&eFork, cudaEventDisableTiming);
    cudaEventCreateWithFlags(&eJoin, cudaEventDisableTiming);

    cudaEventRecord(eFork, 0);
    cudaStreamWaitEvent(s1, eFork, 0);

    k_fuse_w<<<1, HIDDEN, 0, s1>>>(W1, bias, W2, b2);
    k_dot   <<<nb_node, TILE, 0, s1>>>(x);
    cudaEventRecord(eJoin, s1);

    k_count <<<nb_e4, TB>>>(ei);

    cudaStreamWaitEvent(0, eJoin, 0);  // normal edge: covers g_z/g_c from side stream

    // PDL launches: pre-launch while predecessor drains; device-side
    // cudaGridDependencySynchronize() enforces the data dependency.
    cudaLaunchAttribute pdl[1];
    pdl[0].id = cudaLaunchAttributeProgrammaticStreamSerialization;
    pdl[0].val.programmaticStreamSerializationAllowed = 1;

    {
        cudaLaunchConfig_t cfg = {};
        cfg.gridDim  = dim3(nb_n);
        cfg.blockDim = dim3(TB);
        cfg.stream   = 0;
        cfg.attrs    = pdl;
        cfg.numAttrs = 1;
        cudaLaunchKernelEx(&cfg, k_z, out);
    }
    {
        cudaLaunchConfig_t cfg = {};
        cfg.gridDim  = dim3(nb_e4);
        cfg.blockDim = dim3(TB);
        cfg.stream   = 0;
        cfg.attrs    = pdl;
        cfg.numAttrs = 1;
        cudaLaunchKernelEx(&cfg, k_scatter, ei, out);
    }
}